// round 1
// baseline (speedup 1.0000x reference)
#include <cuda_runtime.h>
#include <math.h>

// ---------------- problem constants ----------------
#define TOKENS 4096          // B*S = 2*2048
#define SEQ    2048
#define BATCH  2
#define DMODEL 1024
#define D3     3072
#define FFN    4096
#define NHEAD  16
#define HDIM   64

// ---------------- scratch (device globals; no allocs allowed) ----------------
__device__ float g_qkv    [TOKENS * (size_t)D3];
__device__ float g_attn   [TOKENS * (size_t)DMODEL];
__device__ float g_attnout[TOKENS * (size_t)DMODEL];
__device__ float g_h1     [TOKENS * (size_t)DMODEL];
__device__ float g_ffnh   [TOKENS * (size_t)FFN];
__device__ float g_ffn2   [TOKENS * (size_t)DMODEL];

// =====================================================================
// SGEMM: C[M,N] = A[M,K] @ B[K,N] + bias  (optional ReLU)
// 128x128 tile, BK=8, 256 threads, 8x8 per thread, smem double buffer.
// All dims here are multiples of 128/8 — no bounds checks needed.
// =====================================================================
template<bool RELU>
__global__ __launch_bounds__(256)
void sgemm_bias(const float* __restrict__ A, const float* __restrict__ B,
                const float* __restrict__ bias, float* __restrict__ C,
                int M, int N, int K)
{
    __shared__ float As[2][8][128];   // As[buf][k][m] (transposed)
    __shared__ float Bs[2][8][128];   // Bs[buf][k][n]

    const int tid = threadIdx.x;
    const int bm  = blockIdx.y * 128;
    const int bn  = blockIdx.x * 128;

    // global-load assignments (1 float4 each for A and B per k-tile)
    const int arow = tid >> 1;            // 0..127
    const int acol = (tid & 1) << 2;      // 0 or 4
    const int brow = tid >> 5;            // 0..7
    const int bcol = (tid & 31) << 2;     // 0..124

    const int tx = tid & 15;
    const int ty = tid >> 4;

    const float* Aptr = A + (size_t)(bm + arow) * K + acol;
    const float* Bptr = B + (size_t)brow * N + bn + bcol;

    float acc[8][8] = {};

    // preload tile 0
    float4 a_ld = *(const float4*)Aptr;
    float4 b_ld = *(const float4*)Bptr;
    As[0][acol + 0][arow] = a_ld.x;
    As[0][acol + 1][arow] = a_ld.y;
    As[0][acol + 2][arow] = a_ld.z;
    As[0][acol + 3][arow] = a_ld.w;
    *(float4*)&Bs[0][brow][bcol] = b_ld;
    __syncthreads();

    const int nk = K >> 3;
    int buf = 0;
    for (int t = 0; t < nk; ++t) {
        if (t + 1 < nk) {
            a_ld = *(const float4*)(Aptr + (size_t)(t + 1) * 8);
            b_ld = *(const float4*)(Bptr + (size_t)(t + 1) * 8 * N);
        }
        #pragma unroll
        for (int kk = 0; kk < 8; ++kk) {
            float4 a0 = *(float4*)&As[buf][kk][ty * 8];
            float4 a1 = *(float4*)&As[buf][kk][ty * 8 + 4];
            float4 b0 = *(float4*)&Bs[buf][kk][tx * 8];
            float4 b1 = *(float4*)&Bs[buf][kk][tx * 8 + 4];
            float ar[8] = {a0.x, a0.y, a0.z, a0.w, a1.x, a1.y, a1.z, a1.w};
            float br[8] = {b0.x, b0.y, b0.z, b0.w, b1.x, b1.y, b1.z, b1.w};
            #pragma unroll
            for (int i = 0; i < 8; ++i)
                #pragma unroll
                for (int j = 0; j < 8; ++j)
                    acc[i][j] += ar[i] * br[j];
        }
        if (t + 1 < nk) {
            As[buf ^ 1][acol + 0][arow] = a_ld.x;
            As[buf ^ 1][acol + 1][arow] = a_ld.y;
            As[buf ^ 1][acol + 2][arow] = a_ld.z;
            As[buf ^ 1][acol + 3][arow] = a_ld.w;
            *(float4*)&Bs[buf ^ 1][brow][bcol] = b_ld;
        }
        __syncthreads();
        buf ^= 1;
    }

    // epilogue: bias (+ReLU) + store
    float4 bia0 = *(const float4*)&bias[bn + tx * 8];
    float4 bia1 = *(const float4*)&bias[bn + tx * 8 + 4];
    #pragma unroll
    for (int i = 0; i < 8; ++i) {
        const size_t row = (size_t)(bm + ty * 8 + i);
        float4 c0, c1;
        c0.x = acc[i][0] + bia0.x;  c0.y = acc[i][1] + bia0.y;
        c0.z = acc[i][2] + bia0.z;  c0.w = acc[i][3] + bia0.w;
        c1.x = acc[i][4] + bia1.x;  c1.y = acc[i][5] + bia1.y;
        c1.z = acc[i][6] + bia1.z;  c1.w = acc[i][7] + bia1.w;
        if (RELU) {
            c0.x = fmaxf(c0.x, 0.f); c0.y = fmaxf(c0.y, 0.f);
            c0.z = fmaxf(c0.z, 0.f); c0.w = fmaxf(c0.w, 0.f);
            c1.x = fmaxf(c1.x, 0.f); c1.y = fmaxf(c1.y, 0.f);
            c1.z = fmaxf(c1.z, 0.f); c1.w = fmaxf(c1.w, 0.f);
        }
        *(float4*)&C[row * N + bn + tx * 8]     = c0;
        *(float4*)&C[row * N + bn + tx * 8 + 4] = c1;
    }
}

// =====================================================================
// Fused flash-style attention.
// grid: (SEQ/64, BATCH*NHEAD); 256 threads; each thread owns 4 q-rows x 4 cols.
// qkv layout per token row (3072): head h -> [q(64) | k(64) | v(64)] at h*192.
// out: [token, h*64 + d]
// =====================================================================
#define QS_STR 65
#define KS_STR 65
#define VS_STR 68
#define PS_STR 68
#define QS_OFF 0
#define KS_OFF (64 * QS_STR)                        // 4160
#define VS_OFF (2 * 64 * QS_STR)                    // 8320 (16B aligned)
#define PS_OFF (2 * 64 * QS_STR + 64 * VS_STR)      // 12672 (16B aligned)
#define ATTN_SMEM_FLOATS (2 * 64 * QS_STR + 2 * 64 * VS_STR)   // 17024
#define ATTN_SMEM_BYTES  (ATTN_SMEM_FLOATS * 4)                // 68096

__global__ __launch_bounds__(256)
void attention_kernel(const float* __restrict__ qkv, float* __restrict__ out)
{
    extern __shared__ float sm[];
    float* Qs = sm + QS_OFF;   // Qs[d*65 + r]
    float* Ks = sm + KS_OFF;   // Ks[d*65 + c]
    float* Vs = sm + VS_OFF;   // Vs[k*68 + c]
    float* Ps = sm + PS_OFF;   // Ps[r*68 + k]

    const int tid = threadIdx.x;
    const int b   = blockIdx.y >> 4;
    const int h   = blockIdx.y & 15;
    const int q0  = blockIdx.x << 6;
    const int tx  = tid & 15;
    const int ty  = tid >> 4;
    const int r0  = ty << 2;
    const int c0  = tx << 2;

    const size_t tokbase = (size_t)b * SEQ;
    const int hoff = h * 192;

    // ---- load Q tile, transposed ----
    #pragma unroll
    for (int u = 0; u < 4; ++u) {
        int fid = tid + u * 256;
        int r   = fid >> 4;
        int dg  = (fid & 15) << 2;
        float4 v = *(const float4*)&qkv[(tokbase + q0 + r) * D3 + hoff + dg];
        Qs[(dg + 0) * QS_STR + r] = v.x;
        Qs[(dg + 1) * QS_STR + r] = v.y;
        Qs[(dg + 2) * QS_STR + r] = v.z;
        Qs[(dg + 3) * QS_STR + r] = v.w;
    }

    float m[4], l[4], o[4][4];
    #pragma unroll
    for (int i = 0; i < 4; ++i) {
        m[i] = -1e30f; l[i] = 0.f;
        #pragma unroll
        for (int j = 0; j < 4; ++j) o[i][j] = 0.f;
    }

    for (int kt = 0; kt < SEQ / 64; ++kt) {
        __syncthreads();   // previous iter finished reading Ks/Vs/Ps (covers Q on iter 0)
        // ---- load K (transposed) and V (natural) tiles ----
        #pragma unroll
        for (int u = 0; u < 4; ++u) {
            int fid = tid + u * 256;
            int r   = fid >> 4;
            int dg  = (fid & 15) << 2;
            size_t gaddr = (tokbase + (size_t)kt * 64 + r) * D3 + hoff;
            float4 kv = *(const float4*)&qkv[gaddr + 64 + dg];
            Ks[(dg + 0) * KS_STR + r] = kv.x;
            Ks[(dg + 1) * KS_STR + r] = kv.y;
            Ks[(dg + 2) * KS_STR + r] = kv.z;
            Ks[(dg + 3) * KS_STR + r] = kv.w;
            float4 vv = *(const float4*)&qkv[gaddr + 128 + dg];
            *(float4*)&Vs[r * VS_STR + dg] = vv;
        }
        __syncthreads();

        // ---- S = Q K^T ----
        float s[4][4] = {};
        #pragma unroll 8
        for (int d = 0; d < 64; ++d) {
            float qv[4], kv[4];
            #pragma unroll
            for (int i = 0; i < 4; ++i) qv[i] = Qs[d * QS_STR + r0 + i];
            #pragma unroll
            for (int j = 0; j < 4; ++j) kv[j] = Ks[d * KS_STR + c0 + j];
            #pragma unroll
            for (int i = 0; i < 4; ++i)
                #pragma unroll
                for (int j = 0; j < 4; ++j)
                    s[i][j] += qv[i] * kv[j];
        }

        // ---- online softmax (scale 1/sqrt(64) = 0.125) ----
        #pragma unroll
        for (int i = 0; i < 4; ++i) {
            #pragma unroll
            for (int j = 0; j < 4; ++j) s[i][j] *= 0.125f;
            float rm = fmaxf(fmaxf(s[i][0], s[i][1]), fmaxf(s[i][2], s[i][3]));
            rm = fmaxf(rm, __shfl_xor_sync(0xffffffffu, rm, 1));
            rm = fmaxf(rm, __shfl_xor_sync(0xffffffffu, rm, 2));
            rm = fmaxf(rm, __shfl_xor_sync(0xffffffffu, rm, 4));
            rm = fmaxf(rm, __shfl_xor_sync(0xffffffffu, rm, 8));
            float mn   = fmaxf(m[i], rm);
            float corr = __expf(m[i] - mn);
            float p0 = __expf(s[i][0] - mn);
            float p1 = __expf(s[i][1] - mn);
            float p2 = __expf(s[i][2] - mn);
            float p3 = __expf(s[i][3] - mn);
            float4 pw = make_float4(p0, p1, p2, p3);
            *(float4*)&Ps[(r0 + i) * PS_STR + c0] = pw;
            float rs = p0 + p1 + p2 + p3;
            rs += __shfl_xor_sync(0xffffffffu, rs, 1);
            rs += __shfl_xor_sync(0xffffffffu, rs, 2);
            rs += __shfl_xor_sync(0xffffffffu, rs, 4);
            rs += __shfl_xor_sync(0xffffffffu, rs, 8);
            l[i] = l[i] * corr + rs;
            m[i] = mn;
            #pragma unroll
            for (int j = 0; j < 4; ++j) o[i][j] *= corr;
        }
        __syncthreads();   // Ps visible to all

        // ---- O += P V ----
        #pragma unroll 4
        for (int kk = 0; kk < 64; ++kk) {
            float4 v4 = *(float4*)&Vs[kk * VS_STR + c0];
            #pragma unroll
            for (int i = 0; i < 4; ++i) {
                float p = Ps[(r0 + i) * PS_STR + kk];
                o[i][0] += p * v4.x;
                o[i][1] += p * v4.y;
                o[i][2] += p * v4.z;
                o[i][3] += p * v4.w;
            }
        }
    }

    // ---- normalize + store ----
    #pragma unroll
    for (int i = 0; i < 4; ++i) {
        float inv = 1.f / l[i];
        float4 ov = make_float4(o[i][0] * inv, o[i][1] * inv,
                                o[i][2] * inv, o[i][3] * inv);
        *(float4*)&out[(tokbase + q0 + r0 + i) * DMODEL + h * HDIM + c0] = ov;
    }
}

// =====================================================================
// Fused residual add + LayerNorm over D=1024. One block (256 thr) per row.
// =====================================================================
__global__ __launch_bounds__(256)
void add_ln_kernel(const float* __restrict__ a, const float* __restrict__ res,
                   const float* __restrict__ gamma, const float* __restrict__ beta,
                   float* __restrict__ out)
{
    __shared__ float ss[8], qq[8];
    const int row = blockIdx.x;
    const int tid = threadIdx.x;
    const size_t base = (size_t)row * DMODEL + tid * 4;

    float4 va = *(const float4*)&a[base];
    float4 vr = *(const float4*)&res[base];
    float x0 = va.x + vr.x, x1 = va.y + vr.y, x2 = va.z + vr.z, x3 = va.w + vr.w;

    float s = x0 + x1 + x2 + x3;
    float q = x0 * x0 + x1 * x1 + x2 * x2 + x3 * x3;
    #pragma unroll
    for (int off = 16; off > 0; off >>= 1) {
        s += __shfl_xor_sync(0xffffffffu, s, off);
        q += __shfl_xor_sync(0xffffffffu, q, off);
    }
    const int w = tid >> 5;
    if ((tid & 31) == 0) { ss[w] = s; qq[w] = q; }
    __syncthreads();
    if (tid < 32) {
        float s2 = (tid < 8) ? ss[tid] : 0.f;
        float q2 = (tid < 8) ? qq[tid] : 0.f;
        #pragma unroll
        for (int off = 4; off > 0; off >>= 1) {
            s2 += __shfl_xor_sync(0xffffffffu, s2, off);
            q2 += __shfl_xor_sync(0xffffffffu, q2, off);
        }
        if (tid == 0) { ss[0] = s2; qq[0] = q2; }
    }
    __syncthreads();

    const float mean = ss[0] * (1.f / DMODEL);
    const float var  = qq[0] * (1.f / DMODEL) - mean * mean;
    const float rstd = rsqrtf(var + 1e-5f);

    float4 g  = *(const float4*)&gamma[tid * 4];
    float4 bt = *(const float4*)&beta[tid * 4];
    float4 ov;
    ov.x = (x0 - mean) * rstd * g.x + bt.x;
    ov.y = (x1 - mean) * rstd * g.y + bt.y;
    ov.z = (x2 - mean) * rstd * g.z + bt.z;
    ov.w = (x3 - mean) * rstd * g.w + bt.w;
    *(float4*)&out[base] = ov;
}

// =====================================================================
// kernel_launch
// inputs: x, W_qkv, b_qkv, W_o, b_o, gamma1, beta1, W1, b1, W2, b2, gamma2, beta2
// =====================================================================
extern "C" void kernel_launch(void* const* d_in, const int* in_sizes, int n_in,
                              void* d_out, int out_size)
{
    const float* x      = (const float*)d_in[0];
    const float* W_qkv  = (const float*)d_in[1];
    const float* b_qkv  = (const float*)d_in[2];
    const float* W_o    = (const float*)d_in[3];
    const float* b_o    = (const float*)d_in[4];
    const float* gamma1 = (const float*)d_in[5];
    const float* beta1  = (const float*)d_in[6];
    const float* W1     = (const float*)d_in[7];
    const float* b1     = (const float*)d_in[8];
    const float* W2     = (const float*)d_in[9];
    const float* b2     = (const float*)d_in[10];
    const float* gamma2 = (const float*)d_in[11];
    const float* beta2  = (const float*)d_in[12];
    float* out = (float*)d_out;

    float *qkv, *attn, *attnout, *h1, *ffnh, *ffn2;
    cudaGetSymbolAddress((void**)&qkv,     g_qkv);
    cudaGetSymbolAddress((void**)&attn,    g_attn);
    cudaGetSymbolAddress((void**)&attnout, g_attnout);
    cudaGetSymbolAddress((void**)&h1,      g_h1);
    cudaGetSymbolAddress((void**)&ffnh,    g_ffnh);
    cudaGetSymbolAddress((void**)&ffn2,    g_ffn2);

    cudaFuncSetAttribute(attention_kernel,
                         cudaFuncAttributeMaxDynamicSharedMemorySize,
                         ATTN_SMEM_BYTES);

    dim3 blk(256);

    // 1) qkv = x @ W_qkv + b_qkv                       [4096, 3072]
    sgemm_bias<false><<<dim3(D3 / 128, TOKENS / 128), blk>>>(
        x, W_qkv, b_qkv, qkv, TOKENS, D3, DMODEL);

    // 2) fused attention                               [4096, 1024]
    attention_kernel<<<dim3(SEQ / 64, BATCH * NHEAD), blk, ATTN_SMEM_BYTES>>>(
        qkv, attn);

    // 3) attn_out = attn @ W_o + b_o                   [4096, 1024]
    sgemm_bias<false><<<dim3(DMODEL / 128, TOKENS / 128), blk>>>(
        attn, W_o, b_o, attnout, TOKENS, DMODEL, DMODEL);

    // 4) h1 = LN(attn_out + x)
    add_ln_kernel<<<TOKENS, blk>>>(attnout, x, gamma1, beta1, h1);

    // 5) ffnh = relu(h1 @ W1 + b1)                     [4096, 4096]
    sgemm_bias<true><<<dim3(FFN / 128, TOKENS / 128), blk>>>(
        h1, W1, b1, ffnh, TOKENS, FFN, DMODEL);

    // 6) ffn2 = ffnh @ W2 + b2                         [4096, 1024]
    sgemm_bias<false><<<dim3(DMODEL / 128, TOKENS / 128), blk>>>(
        ffnh, W2, b2, ffn2, TOKENS, DMODEL, FFN);

    // 7) out = LN(ffn2 + h1)
    add_ln_kernel<<<TOKENS, blk>>>(ffn2, h1, gamma2, beta2, out);
}

// round 3
// speedup vs baseline: 1.6161x; 1.6161x over previous
#include <cuda_runtime.h>
#include <cuda_bf16.h>
#include <cstdint>
#include <math.h>

// ---------------- problem constants ----------------
#define TOKENS 4096          // B*S = 2*2048
#define SEQ    2048
#define BATCH  2
#define DMODEL 1024
#define D3     3072
#define FFN    4096
#define NHEAD  16
#define HDIM   64

// ---------------- scratch (device globals; no allocs allowed) ----------------
__device__ float g_qkv    [TOKENS * (size_t)D3];
__device__ float g_attn   [TOKENS * (size_t)DMODEL];
__device__ float g_attnout[TOKENS * (size_t)DMODEL];
__device__ float g_h1     [TOKENS * (size_t)DMODEL];
__device__ float g_ffnh   [TOKENS * (size_t)FFN];
__device__ float g_ffn2   [TOKENS * (size_t)DMODEL];

// =====================================================================
// HMMA helpers (baseline PTX — works on plain sm_103 target)
// =====================================================================
__device__ __forceinline__ uint32_t smem_u32(const void* p) {
    uint32_t a;
    asm("{ .reg .u64 t; cvta.to.shared.u64 t, %1; cvt.u32.u64 %0, t; }"
        : "=r"(a) : "l"(p));
    return a;
}

__device__ __forceinline__ void ldm_x4(uint32_t* r, uint32_t addr) {
    asm volatile("ldmatrix.sync.aligned.m8n8.x4.shared.b16 {%0,%1,%2,%3}, [%4];"
                 : "=r"(r[0]), "=r"(r[1]), "=r"(r[2]), "=r"(r[3]) : "r"(addr));
}

__device__ __forceinline__ void mma_bf16(float* d, const uint32_t* a,
                                         uint32_t b0, uint32_t b1) {
    asm volatile(
        "mma.sync.aligned.m16n8k16.row.col.f32.bf16.bf16.f32 "
        "{%0,%1,%2,%3},{%4,%5,%6,%7},{%8,%9},{%0,%1,%2,%3};"
        : "+f"(d[0]), "+f"(d[1]), "+f"(d[2]), "+f"(d[3])
        : "r"(a[0]), "r"(a[1]), "r"(a[2]), "r"(a[3]), "r"(b0), "r"(b1));
}

__device__ __forceinline__ uint32_t pack_bf16x2_rn(float a, float b) {
    __nv_bfloat162 t = __floats2bfloat162_rn(a, b);
    return *reinterpret_cast<uint32_t*>(&t);
}

// =====================================================================
// HMMA GEMM: C[M,N] = A[M,K] @ B[K,N] + bias (optional ReLU)
// bf16x3 split (Ah*Bh + Ah*Bl + Al*Bh) for ~fp32 accuracy.
// CTA 128x128, BK=32, 8 warps (warp tile 64x32), double-buffered smem.
// smem row stride 80B -> conflict-free ldmatrix wavefronts.
// =====================================================================
#define STRB 80                       // bytes per smem row (32 bf16 + pad)
#define TILE_HB (128 * STRB)          // 10240 B per half-tile
#define BUF_B   (4 * TILE_HB)         // Ah, Al, Bh, Bl = 40960 B
#define GEMM_SMEM (2 * BUF_B)         // 81920 B

template<bool RELU>
__global__ __launch_bounds__(256, 1)
void gemm_mma(const float* __restrict__ A, const float* __restrict__ B,
              const float* __restrict__ bias, float* __restrict__ C,
              int M, int N, int K)
{
    extern __shared__ char smraw[];
    const uint32_t sb = smem_u32(smraw);
    const int tid = threadIdx.x;
    const int l   = tid & 31, w = tid >> 5;
    const int bm  = blockIdx.y * 128, bn = blockIdx.x * 128;
    const int wm  = (w & 1) << 6;     // 0 or 64
    const int wn  = (w >> 1) << 5;    // 0,32,64,96

    // gmem load mapping
    const int arow = tid >> 3;            // + i*32
    const int acg  = (tid & 7) << 2;
    const int bnn  = tid & 127;
    const int bkq0 = tid >> 7;            // 0 or 1

    // ldmatrix lane components
    const int la = l & 15;
    const int lk = (l >> 4) << 3;         // 0 or 8 (elems)

    const int T = K >> 5;

    float4 pa[4];
    float  pb[4][4];
    float  acc[4][4][4];
    #pragma unroll
    for (int i = 0; i < 4; ++i)
        #pragma unroll
        for (int j = 0; j < 4; ++j)
            #pragma unroll
            for (int q = 0; q < 4; ++q) acc[i][j][q] = 0.f;

    // ---------------- helpers ----------------
    auto gload = [&](int k0) {
        #pragma unroll
        for (int i = 0; i < 4; ++i)
            pa[i] = *(const float4*)&A[(size_t)(bm + arow + i * 32) * K + k0 + acg];
        #pragma unroll
        for (int i = 0; i < 4; ++i) {
            const int kq = bkq0 + i * 2;
            const float* p = &B[(size_t)(k0 + (kq << 2)) * N + bn + bnn];
            pb[i][0] = p[0];
            pb[i][1] = p[(size_t)N];
            pb[i][2] = p[(size_t)2 * N];
            pb[i][3] = p[(size_t)3 * N];
        }
    };

    auto split2 = [](float x, float y, uint32_t& hi, uint32_t& lo) {
        uint32_t ux = __float_as_uint(x), uy = __float_as_uint(y);
        hi = __byte_perm(ux, uy, 0x7632);               // truncated bf16 pair
        float rx = x - __uint_as_float(ux & 0xffff0000u);
        float ry = y - __uint_as_float(uy & 0xffff0000u);
        lo = pack_bf16x2_rn(rx, ry);
    };

    auto sstore = [&](int bsel) {
        char* base = smraw + bsel * BUF_B;
        #pragma unroll
        for (int i = 0; i < 4; ++i) {
            uint32_t h01, l01, h23, l23;
            split2(pa[i].x, pa[i].y, h01, l01);
            split2(pa[i].z, pa[i].w, h23, l23);
            uint32_t off = (uint32_t)((arow + i * 32) * STRB + acg * 2);
            *(uint2*)(base + off)           = make_uint2(h01, h23);   // Ah
            *(uint2*)(base + TILE_HB + off) = make_uint2(l01, l23);   // Al
        }
        #pragma unroll
        for (int i = 0; i < 4; ++i) {
            const int kq = bkq0 + i * 2;
            uint32_t h01, l01, h23, l23;
            split2(pb[i][0], pb[i][1], h01, l01);
            split2(pb[i][2], pb[i][3], h23, l23);
            uint32_t off = (uint32_t)(bnn * STRB + kq * 8);
            *(uint2*)(base + 2 * TILE_HB + off) = make_uint2(h01, h23); // Bh
            *(uint2*)(base + 3 * TILE_HB + off) = make_uint2(l01, l23); // Bl
        }
    };

    auto compute = [&](int bsel) {
        const uint32_t base = sb + bsel * BUF_B;
        #pragma unroll
        for (int ks = 0; ks < 2; ++ks) {
            uint32_t ah[4][4], al[4][4], bh[2][4], bl[2][4];
            #pragma unroll
            for (int mf = 0; mf < 4; ++mf) {
                uint32_t off = (uint32_t)((wm + mf * 16 + la) * STRB +
                                          (ks * 16 + lk) * 2);
                ldm_x4(ah[mf], base + off);
                ldm_x4(al[mf], base + TILE_HB + off);
            }
            #pragma unroll
            for (int nf2 = 0; nf2 < 2; ++nf2) {
                uint32_t off = (uint32_t)((wn + nf2 * 16 + la) * STRB +
                                          (ks * 16 + lk) * 2);
                ldm_x4(bh[nf2], base + 2 * TILE_HB + off);
                ldm_x4(bl[nf2], base + 3 * TILE_HB + off);
            }
            #pragma unroll
            for (int mf = 0; mf < 4; ++mf)
                #pragma unroll
                for (int nf = 0; nf < 4; ++nf) {
                    const int g = nf >> 1, s = nf & 1;
                    mma_bf16(acc[mf][nf], ah[mf], bh[g][s], bh[g][2 + s]);
                    mma_bf16(acc[mf][nf], ah[mf], bl[g][s], bl[g][2 + s]);
                    mma_bf16(acc[mf][nf], al[mf], bh[g][s], bh[g][2 + s]);
                }
        }
    };

    // ---------------- pipelined main loop ----------------
    gload(0);
    sstore(0);
    __syncthreads();
    for (int t = 0; t < T; ++t) {
        if (t + 1 < T) gload((t + 1) << 5);
        compute(t & 1);
        if (t + 1 < T) sstore((t + 1) & 1);
        __syncthreads();
    }

    // ---------------- epilogue ----------------
    const int g  = l >> 2;
    const int tg = (l & 3) << 1;
    #pragma unroll
    for (int mf = 0; mf < 4; ++mf) {
        const int r0 = bm + wm + mf * 16 + g;
        #pragma unroll
        for (int nf = 0; nf < 4; ++nf) {
            const int c = bn + wn + nf * 8 + tg;
            float2 bv = *(const float2*)&bias[c];
            float v0 = acc[mf][nf][0] + bv.x;
            float v1 = acc[mf][nf][1] + bv.y;
            float v2 = acc[mf][nf][2] + bv.x;
            float v3 = acc[mf][nf][3] + bv.y;
            if (RELU) {
                v0 = fmaxf(v0, 0.f); v1 = fmaxf(v1, 0.f);
                v2 = fmaxf(v2, 0.f); v3 = fmaxf(v3, 0.f);
            }
            *(float2*)&C[(size_t)r0 * N + c]       = make_float2(v0, v1);
            *(float2*)&C[(size_t)(r0 + 8) * N + c] = make_float2(v2, v3);
        }
    }
}

// =====================================================================
// Fused flash-style attention (unchanged from R1 — R4 target).
// =====================================================================
#define QS_STR 65
#define KS_STR 65
#define VS_STR 68
#define PS_STR 68
#define QS_OFF 0
#define KS_OFF (64 * QS_STR)
#define VS_OFF (2 * 64 * QS_STR)
#define PS_OFF (2 * 64 * QS_STR + 64 * VS_STR)
#define ATTN_SMEM_FLOATS (2 * 64 * QS_STR + 2 * 64 * VS_STR)
#define ATTN_SMEM_BYTES  (ATTN_SMEM_FLOATS * 4)

__global__ __launch_bounds__(256)
void attention_kernel(const float* __restrict__ qkv, float* __restrict__ out)
{
    extern __shared__ float sm[];
    float* Qs = sm + QS_OFF;
    float* Ks = sm + KS_OFF;
    float* Vs = sm + VS_OFF;
    float* Ps = sm + PS_OFF;

    const int tid = threadIdx.x;
    const int b   = blockIdx.y >> 4;
    const int h   = blockIdx.y & 15;
    const int q0  = blockIdx.x << 6;
    const int tx  = tid & 15;
    const int ty  = tid >> 4;
    const int r0  = ty << 2;
    const int c0  = tx << 2;

    const size_t tokbase = (size_t)b * SEQ;
    const int hoff = h * 192;

    #pragma unroll
    for (int u = 0; u < 4; ++u) {
        int fid = tid + u * 256;
        int r   = fid >> 4;
        int dg  = (fid & 15) << 2;
        float4 v = *(const float4*)&qkv[(tokbase + q0 + r) * D3 + hoff + dg];
        Qs[(dg + 0) * QS_STR + r] = v.x;
        Qs[(dg + 1) * QS_STR + r] = v.y;
        Qs[(dg + 2) * QS_STR + r] = v.z;
        Qs[(dg + 3) * QS_STR + r] = v.w;
    }

    float m[4], lsum[4], o[4][4];
    #pragma unroll
    for (int i = 0; i < 4; ++i) {
        m[i] = -1e30f; lsum[i] = 0.f;
        #pragma unroll
        for (int j = 0; j < 4; ++j) o[i][j] = 0.f;
    }

    for (int kt = 0; kt < SEQ / 64; ++kt) {
        __syncthreads();
        #pragma unroll
        for (int u = 0; u < 4; ++u) {
            int fid = tid + u * 256;
            int r   = fid >> 4;
            int dg  = (fid & 15) << 2;
            size_t gaddr = (tokbase + (size_t)kt * 64 + r) * D3 + hoff;
            float4 kv = *(const float4*)&qkv[gaddr + 64 + dg];
            Ks[(dg + 0) * KS_STR + r] = kv.x;
            Ks[(dg + 1) * KS_STR + r] = kv.y;
            Ks[(dg + 2) * KS_STR + r] = kv.z;
            Ks[(dg + 3) * KS_STR + r] = kv.w;
            float4 vv = *(const float4*)&qkv[gaddr + 128 + dg];
            *(float4*)&Vs[r * VS_STR + dg] = vv;
        }
        __syncthreads();

        float s[4][4] = {};
        #pragma unroll 8
        for (int d = 0; d < 64; ++d) {
            float qv[4], kv[4];
            #pragma unroll
            for (int i = 0; i < 4; ++i) qv[i] = Qs[d * QS_STR + r0 + i];
            #pragma unroll
            for (int j = 0; j < 4; ++j) kv[j] = Ks[d * KS_STR + c0 + j];
            #pragma unroll
            for (int i = 0; i < 4; ++i)
                #pragma unroll
                for (int j = 0; j < 4; ++j)
                    s[i][j] += qv[i] * kv[j];
        }

        #pragma unroll
        for (int i = 0; i < 4; ++i) {
            #pragma unroll
            for (int j = 0; j < 4; ++j) s[i][j] *= 0.125f;
            float rm = fmaxf(fmaxf(s[i][0], s[i][1]), fmaxf(s[i][2], s[i][3]));
            rm = fmaxf(rm, __shfl_xor_sync(0xffffffffu, rm, 1));
            rm = fmaxf(rm, __shfl_xor_sync(0xffffffffu, rm, 2));
            rm = fmaxf(rm, __shfl_xor_sync(0xffffffffu, rm, 4));
            rm = fmaxf(rm, __shfl_xor_sync(0xffffffffu, rm, 8));
            float mn   = fmaxf(m[i], rm);
            float corr = __expf(m[i] - mn);
            float p0 = __expf(s[i][0] - mn);
            float p1 = __expf(s[i][1] - mn);
            float p2 = __expf(s[i][2] - mn);
            float p3 = __expf(s[i][3] - mn);
            *(float4*)&Ps[(r0 + i) * PS_STR + c0] = make_float4(p0, p1, p2, p3);
            float rs = p0 + p1 + p2 + p3;
            rs += __shfl_xor_sync(0xffffffffu, rs, 1);
            rs += __shfl_xor_sync(0xffffffffu, rs, 2);
            rs += __shfl_xor_sync(0xffffffffu, rs, 4);
            rs += __shfl_xor_sync(0xffffffffu, rs, 8);
            lsum[i] = lsum[i] * corr + rs;
            m[i] = mn;
            #pragma unroll
            for (int j = 0; j < 4; ++j) o[i][j] *= corr;
        }
        __syncthreads();

        #pragma unroll 4
        for (int kk = 0; kk < 64; ++kk) {
            float4 v4 = *(float4*)&Vs[kk * VS_STR + c0];
            #pragma unroll
            for (int i = 0; i < 4; ++i) {
                float p = Ps[(r0 + i) * PS_STR + kk];
                o[i][0] += p * v4.x;
                o[i][1] += p * v4.y;
                o[i][2] += p * v4.z;
                o[i][3] += p * v4.w;
            }
        }
    }

    #pragma unroll
    for (int i = 0; i < 4; ++i) {
        float inv = 1.f / lsum[i];
        *(float4*)&out[(tokbase + q0 + r0 + i) * DMODEL + h * HDIM + c0] =
            make_float4(o[i][0] * inv, o[i][1] * inv, o[i][2] * inv, o[i][3] * inv);
    }
}

// =====================================================================
// Fused residual add + LayerNorm (unchanged).
// =====================================================================
__global__ __launch_bounds__(256)
void add_ln_kernel(const float* __restrict__ a, const float* __restrict__ res,
                   const float* __restrict__ gamma, const float* __restrict__ beta,
                   float* __restrict__ out)
{
    __shared__ float ss[8], qq[8];
    const int row = blockIdx.x;
    const int tid = threadIdx.x;
    const size_t base = (size_t)row * DMODEL + tid * 4;

    float4 va = *(const float4*)&a[base];
    float4 vr = *(const float4*)&res[base];
    float x0 = va.x + vr.x, x1 = va.y + vr.y, x2 = va.z + vr.z, x3 = va.w + vr.w;

    float s = x0 + x1 + x2 + x3;
    float q = x0 * x0 + x1 * x1 + x2 * x2 + x3 * x3;
    #pragma unroll
    for (int off = 16; off > 0; off >>= 1) {
        s += __shfl_xor_sync(0xffffffffu, s, off);
        q += __shfl_xor_sync(0xffffffffu, q, off);
    }
    const int w = tid >> 5;
    if ((tid & 31) == 0) { ss[w] = s; qq[w] = q; }
    __syncthreads();
    if (tid < 32) {
        float s2 = (tid < 8) ? ss[tid] : 0.f;
        float q2 = (tid < 8) ? qq[tid] : 0.f;
        #pragma unroll
        for (int off = 4; off > 0; off >>= 1) {
            s2 += __shfl_xor_sync(0xffffffffu, s2, off);
            q2 += __shfl_xor_sync(0xffffffffu, q2, off);
        }
        if (tid == 0) { ss[0] = s2; qq[0] = q2; }
    }
    __syncthreads();

    const float mean = ss[0] * (1.f / DMODEL);
    const float var  = qq[0] * (1.f / DMODEL) - mean * mean;
    const float rstd = rsqrtf(var + 1e-5f);

    float4 g  = *(const float4*)&gamma[tid * 4];
    float4 bt = *(const float4*)&beta[tid * 4];
    float4 ov;
    ov.x = (x0 - mean) * rstd * g.x + bt.x;
    ov.y = (x1 - mean) * rstd * g.y + bt.y;
    ov.z = (x2 - mean) * rstd * g.z + bt.z;
    ov.w = (x3 - mean) * rstd * g.w + bt.w;
    *(float4*)&out[base] = ov;
}

// =====================================================================
// kernel_launch
// =====================================================================
extern "C" void kernel_launch(void* const* d_in, const int* in_sizes, int n_in,
                              void* d_out, int out_size)
{
    const float* x      = (const float*)d_in[0];
    const float* W_qkv  = (const float*)d_in[1];
    const float* b_qkv  = (const float*)d_in[2];
    const float* W_o    = (const float*)d_in[3];
    const float* b_o    = (const float*)d_in[4];
    const float* gamma1 = (const float*)d_in[5];
    const float* beta1  = (const float*)d_in[6];
    const float* W1     = (const float*)d_in[7];
    const float* b1     = (const float*)d_in[8];
    const float* W2     = (const float*)d_in[9];
    const float* b2     = (const float*)d_in[10];
    const float* gamma2 = (const float*)d_in[11];
    const float* beta2  = (const float*)d_in[12];
    float* out = (float*)d_out;

    float *qkv, *attn, *attnout, *h1, *ffnh, *ffn2;
    cudaGetSymbolAddress((void**)&qkv,     g_qkv);
    cudaGetSymbolAddress((void**)&attn,    g_attn);
    cudaGetSymbolAddress((void**)&attnout, g_attnout);
    cudaGetSymbolAddress((void**)&h1,      g_h1);
    cudaGetSymbolAddress((void**)&ffnh,    g_ffnh);
    cudaGetSymbolAddress((void**)&ffn2,    g_ffn2);

    cudaFuncSetAttribute(attention_kernel,
                         cudaFuncAttributeMaxDynamicSharedMemorySize,
                         ATTN_SMEM_BYTES);
    cudaFuncSetAttribute(gemm_mma<false>,
                         cudaFuncAttributeMaxDynamicSharedMemorySize, GEMM_SMEM);
    cudaFuncSetAttribute(gemm_mma<true>,
                         cudaFuncAttributeMaxDynamicSharedMemorySize, GEMM_SMEM);

    dim3 blk(256);

    // 1) qkv = x @ W_qkv + b_qkv                       [4096, 3072]
    gemm_mma<false><<<dim3(D3 / 128, TOKENS / 128), blk, GEMM_SMEM>>>(
        x, W_qkv, b_qkv, qkv, TOKENS, D3, DMODEL);

    // 2) fused attention                               [4096, 1024]
    attention_kernel<<<dim3(SEQ / 64, BATCH * NHEAD), blk, ATTN_SMEM_BYTES>>>(
        qkv, attn);

    // 3) attn_out = attn @ W_o + b_o                   [4096, 1024]
    gemm_mma<false><<<dim3(DMODEL / 128, TOKENS / 128), blk, GEMM_SMEM>>>(
        attn, W_o, b_o, attnout, TOKENS, DMODEL, DMODEL);

    // 4) h1 = LN(attn_out + x)
    add_ln_kernel<<<TOKENS, blk>>>(attnout, x, gamma1, beta1, h1);

    // 5) ffnh = relu(h1 @ W1 + b1)                     [4096, 4096]
    gemm_mma<true><<<dim3(FFN / 128, TOKENS / 128), blk, GEMM_SMEM>>>(
        h1, W1, b1, ffnh, TOKENS, FFN, DMODEL);

    // 6) ffn2 = ffnh @ W2 + b2                         [4096, 1024]
    gemm_mma<false><<<dim3(DMODEL / 128, TOKENS / 128), blk, GEMM_SMEM>>>(
        ffnh, W2, b2, ffn2, TOKENS, DMODEL, FFN);

    // 7) out = LN(ffn2 + h1)
    add_ln_kernel<<<TOKENS, blk>>>(ffn2, h1, gamma2, beta2, out);
}